// round 8
// baseline (speedup 1.0000x reference)
#include <cuda_runtime.h>
#include <cuda_fp16.h>
#include <cstdint>

// Problem constants
#define A_CAPS   32
#define CDIM     16
#define KKA      288          // 9 * 32
#define KHALF    144          // per cluster rank
#define JD       512          // B*D
#define OH       15
#define OW       15
#define LPOS     225          // OH*OW
#define BATCH    4
#define MTOT     900          // BATCH * LPOS
#define M_TILE   60           // 900 / 60 = 15 tiles
#define WS_STR   516          // padded row stride for Ws [c][jd]

// K2 dynamic smem layout (bytes)
#define SV_BYTES     (KHALF * JD * 2)            // 147456 fp16 votes half-tile
#define LG_BYTES     (KHALF * 32 * 4)            // 18432 logits
#define PART_FLTS    (2 * 2 * JD)                // [buf][slot][jd]
#define K2_SMEM_BYTES (SV_BYTES + LG_BYTES + (PART_FLTS + JD + 256 + 32) * 4)

// 265 MB votes scratch (fp16): [m][k][jd]
__device__ __align__(16) __half g_votes[(size_t)MTOT * KKA * JD];

// ---- packed f32x2 helpers (sm_103a FFMA2) ----
__device__ __forceinline__ unsigned long long pk2(float x, float y) {
    unsigned long long r;
    asm("mov.b64 %0, {%1, %2};" : "=l"(r) : "f"(x), "f"(y));
    return r;
}
__device__ __forceinline__ unsigned long long ffma2(
    unsigned long long a, unsigned long long b, unsigned long long c) {
    unsigned long long d;
    asm("fma.rn.f32x2 %0, %1, %2, %3;" : "=l"(d) : "l"(a), "l"(b), "l"(c));
    return d;
}
__device__ __forceinline__ void upk2(unsigned long long v, float& lo, float& hi) {
    asm("mov.b64 {%0, %1}, %2;" : "=f"(lo), "=f"(hi) : "l"(v));
}
__device__ __forceinline__ uint32_t smem_u32(const void* p) {
    uint32_t a;
    asm("{ .reg .u64 t; cvta.to.shared.u64 t, %1; cvt.u32.u64 %0, t; }"
        : "=r"(a) : "l"(p));
    return a;
}

// ---------------------------------------------------------------------------
// K1: votes[m][k][jd] = sum_c W[k][jd][c] * p[m][k][c]   (f32x2 math, fp16 out)
// W slice in registers; pose PRE-PACKED as (p,p) u64 in smem -> inner loop is
// 8 LDS.128 + 32 FFMA2 per m-step.
// grid (KKA, MTOT/M_TILE), 256 threads
// ---------------------------------------------------------------------------
__global__ void __launch_bounds__(256, 2) votes_kernel(
    const float* __restrict__ pose, const float* __restrict__ W)
{
    __shared__ __align__(16) float Ws[CDIM * WS_STR];            // [c][jd]
    __shared__ __align__(16) unsigned long long Ps2[M_TILE][CDIM]; // (p,p) packed

    const int k  = blockIdx.x;
    const int m0 = blockIdx.y * M_TILE;
    const int t  = threadIdx.x;

    // Stage W[k] (512x16) transposed into smem
    const float* Wk = W + (size_t)k * (JD * CDIM);
    for (int i = t; i < JD * CDIM; i += 256) {
        int jd = i >> 4, c = i & 15;
        Ws[c * WS_STR + jd] = Wk[i];
    }

    // Stage pose slices, pre-packed (p,p)
    const int a  = k & 31;
    const int kk = k >> 5;
    const int ki = kk / 3, kj = kk % 3;
    for (int i = t; i < M_TILE * CDIM; i += 256) {
        int mi = i >> 4, c = i & 15;
        int m  = m0 + mi;
        int b  = m / LPOS, l = m % LPOS;
        int oy = l / OW,   ox = l % OW;
        int y  = 2 * oy + ki, x = 2 * ox + kj;
        float p = pose[(((size_t)b * (A_CAPS * CDIM) + a * CDIM + c) * 32 + y) * 32 + x];
        Ps2[mi][c] = pk2(p, p);
    }
    __syncthreads();

    const int jdg   = t & 127;     // jd group of 4: jd = 4*jdg
    const int mslot = t >> 7;      // 0 or 1

    // Hoist this thread's W slice into packed registers (one-time)
    unsigned long long w01[CDIM], w23[CDIM];
    #pragma unroll
    for (int c = 0; c < CDIM; c++) {
        float4 w4 = *reinterpret_cast<const float4*>(&Ws[c * WS_STR + 4 * jdg]);
        w01[c] = pk2(w4.x, w4.y);
        w23[c] = pk2(w4.z, w4.w);
    }

    #pragma unroll 2
    for (int q = 0; q < M_TILE / 2; q++) {
        const int mi = 2 * q + mslot;
        const ulonglong2* pp = reinterpret_cast<const ulonglong2*>(&Ps2[mi][0]);
        unsigned long long a01 = 0ull, a23 = 0ull;
        #pragma unroll
        for (int cc = 0; cc < CDIM / 2; cc++) {
            ulonglong2 p2 = pp[cc];                 // LDS.128 broadcast
            a01 = ffma2(w01[2 * cc],     p2.x, a01);
            a23 = ffma2(w23[2 * cc],     p2.x, a23);
            a01 = ffma2(w01[2 * cc + 1], p2.y, a01);
            a23 = ffma2(w23[2 * cc + 1], p2.y, a23);
        }
        float x0, x1, x2, x3;
        upk2(a01, x0, x1);
        upk2(a23, x2, x3);
        __half2 h0 = __floats2half2_rn(x0, x1);
        __half2 h1 = __floats2half2_rn(x2, x3);
        uint2 st;
        st.x = *reinterpret_cast<uint32_t*>(&h0);
        st.y = *reinterpret_cast<uint32_t*>(&h1);
        *reinterpret_cast<uint2*>(
            &g_votes[((size_t)(m0 + mi) * KKA + k) * JD + 4 * jdg]) = st;
    }
}

// ---------------------------------------------------------------------------
// K2: routing, 2-CTA cluster per site. Each rank holds 144 k-rows of votes in
// smem (loaded from DRAM once). Partial-s exchanged via DSMEM per iteration.
// 256 threads; thread t owns jd pair (2t, 2t+1), capsule j = t>>3.
// ---------------------------------------------------------------------------

// exchange partial s across the pair; returns identical total in both ranks
__device__ __forceinline__ float2 exchange_partial(
    float* pbuf /* [2][JD] */, int rank, int t, float2 s)
{
    pbuf[rank * JD + 2 * t]     = s.x;
    pbuf[rank * JD + 2 * t + 1] = s.y;
    uint32_t a = smem_u32(&pbuf[rank * JD + 2 * t]);
    unsigned long long pv = pk2(s.x, s.y);
    asm volatile(
        "{ .reg .b32 r; mapa.shared::cluster.u32 r, %0, %1;"
        "  st.shared::cluster.b64 [r], %2; }"
        :: "r"(a), "r"(rank ^ 1), "l"(pv) : "memory");
    asm volatile("barrier.cluster.arrive.aligned;" ::: "memory");
    asm volatile("barrier.cluster.wait.aligned;" ::: "memory");
    float2 tot;
    tot.x = pbuf[2 * t]     + pbuf[JD + 2 * t];
    tot.y = pbuf[2 * t + 1] + pbuf[JD + 2 * t + 1];
    return tot;
}

__device__ __forceinline__ void squash_store(
    float2 s, int t, int j, int lane8, float* n2_s, float* v_s)
{
    float q = s.x * s.x + s.y * s.y;
    #pragma unroll
    for (int off = 4; off > 0; off >>= 1)
        q += __shfl_down_sync(0xffffffffu, q, off, 8);
    if (lane8 == 0) n2_s[j] = q;
    __syncthreads();
    float n2 = n2_s[j];
    float f  = n2 / ((1.f + n2) * sqrtf(n2 + 1e-8f));
    v_s[2 * t]     = s.x * f;
    v_s[2 * t + 1] = s.y * f;
    __syncthreads();
}

template <bool FIRST>
__device__ __forceinline__ float2 route_pass_smem(
    const __half* __restrict__ sv,
    float* logits, float* c_s, float* v_s,
    int t, int j)
{
    const float2 vv = make_float2(v_s[2 * t], v_s[2 * t + 1]);
    float2 sa = make_float2(0.f, 0.f);
    const int w = t >> 5, lane = t & 31;
    const int lane8 = t & 7;

    for (int kc = 0; kc < KHALF; kc += 8) {
        float2 vt[8];
        #pragma unroll
        for (int i = 0; i < 8; i++) {
            __half2 h = *reinterpret_cast<const __half2*>(
                sv + (kc + i) * JD + 2 * t);
            vt[i] = __half22float2(h);
        }
        #pragma unroll
        for (int i = 0; i < 8; i++) {
            float d = vt[i].x * vv.x + vt[i].y * vv.y;
            #pragma unroll
            for (int off = 4; off > 0; off >>= 1)
                d += __shfl_down_sync(0xffffffffu, d, off, 8);
            if (lane8 == 0) {
                int idx = (kc + i) * 32 + j;
                if (FIRST) logits[idx] = d;
                else       logits[idx] += d;
            }
        }
        __syncthreads();
        // softmax over B=32 for the 8 rows, one warp per row
        {
            float lg = logits[(kc + w) * 32 + lane];
            float mx = lg;
            #pragma unroll
            for (int off = 16; off > 0; off >>= 1)
                mx = fmaxf(mx, __shfl_xor_sync(0xffffffffu, mx, off));
            float e = __expf(lg - mx);
            float sm = e;
            #pragma unroll
            for (int off = 16; off > 0; off >>= 1)
                sm += __shfl_xor_sync(0xffffffffu, sm, off);
            c_s[w * 32 + lane] = e / sm;
        }
        __syncthreads();
        #pragma unroll
        for (int i = 0; i < 8; i++) {
            float c = c_s[i * 32 + j];
            sa.x += c * vt[i].x;
            sa.y += c * vt[i].y;
        }
    }
    return sa;
}

__global__ void __launch_bounds__(256, 1) __cluster_dims__(2, 1, 1)
routing_kernel(float* __restrict__ out)
{
    extern __shared__ __align__(16) char smraw[];
    __half* sv    = reinterpret_cast<__half*>(smraw);            // 144x512 fp16
    float* logits = reinterpret_cast<float*>(smraw + SV_BYTES);  // 144x32
    float* part   = logits + KHALF * 32;                         // [2][2][JD]
    float* v_s    = part + PART_FLTS;                            // 512
    float* c_s    = v_s + JD;                                    // 256
    float* n2_s   = c_s + 256;                                   // 32

    const int rank = blockIdx.x & 1;
    const int m    = blockIdx.x >> 1;
    const int t    = threadIdx.x;
    const int j    = t >> 3;
    const int lane8 = t & 7;

    const __half* base = g_votes + (size_t)m * (KKA * JD) + (size_t)rank * KHALF * JD;

    // ---- load half-tile into smem (single DRAM pass), uint4 copy ----
    {
        const uint4* g  = reinterpret_cast<const uint4*>(base);
        uint4* s4 = reinterpret_cast<uint4*>(sv);
        #pragma unroll 4
        for (int i = t; i < SV_BYTES / 16; i += 256)
            s4[i] = g[i];
    }
    __syncthreads();

    // ---- iteration 1: s = (sum over all 288 k) / 32 ----
    float2 s = make_float2(0.f, 0.f);
    #pragma unroll 8
    for (int k = 0; k < KHALF; k++) {
        __half2 h = *reinterpret_cast<const __half2*>(sv + k * JD + 2 * t);
        float2 f = __half22float2(h);
        s.x += f.x; s.y += f.y;
    }
    s = exchange_partial(part + 0 * 2 * JD, rank, t, s);
    s.x *= (1.f / 32.f);
    s.y *= (1.f / 32.f);
    squash_store(s, t, j, lane8, n2_s, v_s);                      // v1

    // ---- iteration 2 ----
    float2 s2 = route_pass_smem<true>(sv, logits, c_s, v_s, t, j);
    s2 = exchange_partial(part + 1 * 2 * JD, rank, t, s2);
    squash_store(s2, t, j, lane8, n2_s, v_s);                     // v2

    // ---- iteration 3 ----
    float2 s3 = route_pass_smem<false>(sv, logits, c_s, v_s, t, j);
    s3 = exchange_partial(part + 0 * 2 * JD, rank, t, s3);
    squash_store(s3, t, j, lane8, n2_s, v_s);                     // v3

    // output: out[b, jd, l] — rank 0 writes all 512 jd
    if (rank == 0) {
        const int b = m / LPOS, l = m % LPOS;
        out[((size_t)b * JD + 2 * t) * LPOS + l]     = v_s[2 * t];
        out[((size_t)b * JD + 2 * t + 1) * LPOS + l] = v_s[2 * t + 1];
    }
}

// ---------------------------------------------------------------------------
extern "C" void kernel_launch(void* const* d_in, const int* in_sizes, int n_in,
                              void* d_out, int out_size)
{
    const float* pose = (const float*)d_in[0];   // (4, 512, 32, 32)
    const float* W    = (const float*)d_in[1];   // (288, 512, 16)
    float* out        = (float*)d_out;           // (4, 512, 15, 15)

    cudaFuncSetAttribute(routing_kernel,
                         cudaFuncAttributeMaxDynamicSharedMemorySize,
                         K2_SMEM_BYTES);

    dim3 g1(KKA, MTOT / M_TILE);
    votes_kernel<<<g1, 256>>>(pose, W);
    routing_kernel<<<2 * MTOT, 256, K2_SMEM_BYTES>>>(out);
}

// round 11
// speedup vs baseline: 1.0069x; 1.0069x over previous
#include <cuda_runtime.h>
#include <cuda_fp16.h>
#include <cstdint>

// Problem constants
#define A_CAPS   32
#define CDIM     16
#define KKA      288          // 9 * 32
#define KHALF    144          // per cluster rank
#define ROWS_PW  18           // KHALF / 8 warps
#define JD       512          // B*D
#define OH       15
#define OW       15
#define LPOS     225          // OH*OW
#define BATCH    4
#define MTOT     900          // BATCH * LPOS
#define M_TILE   60           // 900 / 60 = 15 tiles
#define WS_STR   516          // padded row stride for Ws [c][jd]

// K2 dynamic smem layout (bytes)
#define SV_BYTES   (KHALF * JD * 2)        // 147456 fp16 votes half-tile
#define SP_BYTES   (8 * JD * 4)            // 16384 cross-warp partials
#define PART_BYTES (2 * 2 * JD * 4)        // 8192  [buf][rank][jd] exchange
#define K2_SMEM_BYTES (SV_BYTES + SP_BYTES + PART_BYTES)

// 265 MB votes scratch (fp16): [m][k][jd]
__device__ __align__(16) __half g_votes[(size_t)MTOT * KKA * JD];

// ---- packed f32x2 helpers (sm_103a) ----
__device__ __forceinline__ unsigned long long pk2(float x, float y) {
    unsigned long long r;
    asm("mov.b64 %0, {%1, %2};" : "=l"(r) : "f"(x), "f"(y));
    return r;
}
__device__ __forceinline__ unsigned long long ffma2(
    unsigned long long a, unsigned long long b, unsigned long long c) {
    unsigned long long d;
    asm("fma.rn.f32x2 %0, %1, %2, %3;" : "=l"(d) : "l"(a), "l"(b), "l"(c));
    return d;
}
__device__ __forceinline__ void upk2(unsigned long long v, float& lo, float& hi) {
    asm("mov.b64 {%0, %1}, %2;" : "=f"(lo), "=f"(hi) : "l"(v));
}
__device__ __forceinline__ uint32_t smem_u32(const void* p) {
    uint32_t a;
    asm("{ .reg .u64 t; cvta.to.shared.u64 t, %1; cvt.u32.u64 %0, t; }"
        : "=r"(a) : "l"(p));
    return a;
}

// ---------------------------------------------------------------------------
// K1 (unchanged): votes[m][k][jd] = sum_c W[k][jd][c] * p[m][k][c]
// ---------------------------------------------------------------------------
__global__ void __launch_bounds__(256, 2) votes_kernel(
    const float* __restrict__ pose, const float* __restrict__ W)
{
    __shared__ __align__(16) float Ws[CDIM * WS_STR];
    __shared__ __align__(16) unsigned long long Ps2[M_TILE][CDIM];

    const int k  = blockIdx.x;
    const int m0 = blockIdx.y * M_TILE;
    const int t  = threadIdx.x;

    const float* Wk = W + (size_t)k * (JD * CDIM);
    for (int i = t; i < JD * CDIM; i += 256) {
        int jd = i >> 4, c = i & 15;
        Ws[c * WS_STR + jd] = Wk[i];
    }

    const int a  = k & 31;
    const int kk = k >> 5;
    const int ki = kk / 3, kj = kk % 3;
    for (int i = t; i < M_TILE * CDIM; i += 256) {
        int mi = i >> 4, c = i & 15;
        int m  = m0 + mi;
        int b  = m / LPOS, l = m % LPOS;
        int oy = l / OW,   ox = l % OW;
        int y  = 2 * oy + ki, x = 2 * ox + kj;
        float p = pose[(((size_t)b * (A_CAPS * CDIM) + a * CDIM + c) * 32 + y) * 32 + x];
        Ps2[mi][c] = pk2(p, p);
    }
    __syncthreads();

    const int jdg   = t & 127;
    const int mslot = t >> 7;

    unsigned long long w01[CDIM], w23[CDIM];
    #pragma unroll
    for (int c = 0; c < CDIM; c++) {
        float4 w4 = *reinterpret_cast<const float4*>(&Ws[c * WS_STR + 4 * jdg]);
        w01[c] = pk2(w4.x, w4.y);
        w23[c] = pk2(w4.z, w4.w);
    }

    #pragma unroll 2
    for (int q = 0; q < M_TILE / 2; q++) {
        const int mi = 2 * q + mslot;
        const ulonglong2* pp = reinterpret_cast<const ulonglong2*>(&Ps2[mi][0]);
        unsigned long long a01 = 0ull, a23 = 0ull;
        #pragma unroll
        for (int cc = 0; cc < CDIM / 2; cc++) {
            ulonglong2 p2 = pp[cc];
            a01 = ffma2(w01[2 * cc],     p2.x, a01);
            a23 = ffma2(w23[2 * cc],     p2.x, a23);
            a01 = ffma2(w01[2 * cc + 1], p2.y, a01);
            a23 = ffma2(w23[2 * cc + 1], p2.y, a23);
        }
        float x0, x1, x2, x3;
        upk2(a01, x0, x1);
        upk2(a23, x2, x3);
        __half2 h0 = __floats2half2_rn(x0, x1);
        __half2 h1 = __floats2half2_rn(x2, x3);
        uint2 st;
        st.x = *reinterpret_cast<uint32_t*>(&h0);
        st.y = *reinterpret_cast<uint32_t*>(&h1);
        *reinterpret_cast<uint2*>(
            &g_votes[((size_t)(m0 + mi) * KKA + k) * JD + 4 * jdg]) = st;
    }
}

// ---------------------------------------------------------------------------
// K2 v3: 2-CTA cluster per site; votes half-tile in smem (one DRAM pass).
// WARP-AUTONOMOUS routing: warp w owns k-rows [w*18, w*18+18), lane j owns
// capsule j (jd 16j..16j+15). No block barriers inside the k-loop.
// ---------------------------------------------------------------------------

__device__ __forceinline__ void load_row(const __half* sv, int k, int j,
                                         uint4& q0, uint4& q1)
{
    const uint4* p = reinterpret_cast<const uint4*>(sv + k * JD + 16 * j);
    q0 = p[0];
    q1 = p[1];
}

__device__ __forceinline__ void cvt_row(const uint4& q0, const uint4& q1, float* row)
{
    const uint32_t u[8] = {q0.x, q0.y, q0.z, q0.w, q1.x, q1.y, q1.z, q1.w};
    #pragma unroll
    for (int i = 0; i < 8; i++) {
        float2 f = __half22float2(*reinterpret_cast<const __half2*>(&u[i]));
        row[2 * i]     = f.x;
        row[2 * i + 1] = f.y;
    }
}

// cross-warp + cross-rank reduction of per-lane 16-float partials.
// Every thread returns the full-site total for its 16 jd.
__device__ __forceinline__ void reduce_site(
    float* sacc /* in: this warp's partial; out: site total */,
    float* s_part, float* part, int buf, int rank, int w, int j, int t)
{
    // stage this warp's partial
    float4* dst = reinterpret_cast<float4*>(s_part + w * JD + 16 * j);
    dst[0] = make_float4(sacc[0], sacc[1], sacc[2],  sacc[3]);
    dst[1] = make_float4(sacc[4], sacc[5], sacc[6],  sacc[7]);
    dst[2] = make_float4(sacc[8], sacc[9], sacc[10], sacc[11]);
    dst[3] = make_float4(sacc[12], sacc[13], sacc[14], sacc[15]);
    __syncthreads();

    // cross-warp sum (every thread, redundant across warps -> identical)
    float tot[16];
    #pragma unroll
    for (int d = 0; d < 16; d++) tot[d] = 0.f;
    #pragma unroll
    for (int ww = 0; ww < 8; ww++) {
        const float4* sp = reinterpret_cast<const float4*>(s_part + ww * JD + 16 * j);
        float4 a0 = sp[0], a1 = sp[1], a2 = sp[2], a3 = sp[3];
        tot[0] += a0.x;  tot[1] += a0.y;  tot[2] += a0.z;  tot[3] += a0.w;
        tot[4] += a1.x;  tot[5] += a1.y;  tot[6] += a1.z;  tot[7] += a1.w;
        tot[8] += a2.x;  tot[9] += a2.y;  tot[10] += a2.z; tot[11] += a2.w;
        tot[12] += a3.x; tot[13] += a3.y; tot[14] += a3.z; tot[15] += a3.w;
    }

    // cross-rank exchange: warp 0 publishes rank slice locally + to peer
    float* slot = part + (buf * 2 + rank) * JD;  // [buf][rank][jd]
    if (w == 0) {
        float4* lp = reinterpret_cast<float4*>(slot + 16 * j);
        lp[0] = make_float4(tot[0], tot[1], tot[2],  tot[3]);
        lp[1] = make_float4(tot[4], tot[5], tot[6],  tot[7]);
        lp[2] = make_float4(tot[8], tot[9], tot[10], tot[11]);
        lp[3] = make_float4(tot[12], tot[13], tot[14], tot[15]);
        uint32_t la = smem_u32(slot + 16 * j);
        #pragma unroll
        for (int d = 0; d < 8; d++) {
            unsigned long long pv = pk2(tot[2 * d], tot[2 * d + 1]);
            asm volatile(
                "{ .reg .b32 r; mapa.shared::cluster.u32 r, %0, %1;"
                "  st.shared::cluster.b64 [r], %2; }"
                :: "r"(la + 8 * d), "r"(rank ^ 1), "l"(pv) : "memory");
        }
    }
    asm volatile("barrier.cluster.arrive.aligned;" ::: "memory");
    asm volatile("barrier.cluster.wait.aligned;" ::: "memory");

    // add peer slice
    const float* pslot = part + (buf * 2 + (rank ^ 1)) * JD;
    const float4* pp = reinterpret_cast<const float4*>(pslot + 16 * j);
    float4 b0 = pp[0], b1 = pp[1], b2 = pp[2], b3 = pp[3];
    sacc[0]  = tot[0] + b0.x;  sacc[1]  = tot[1] + b0.y;
    sacc[2]  = tot[2] + b0.z;  sacc[3]  = tot[3] + b0.w;
    sacc[4]  = tot[4] + b1.x;  sacc[5]  = tot[5] + b1.y;
    sacc[6]  = tot[6] + b1.z;  sacc[7]  = tot[7] + b1.w;
    sacc[8]  = tot[8] + b2.x;  sacc[9]  = tot[9] + b2.y;
    sacc[10] = tot[10] + b2.z; sacc[11] = tot[11] + b2.w;
    sacc[12] = tot[12] + b3.x; sacc[13] = tot[13] + b3.y;
    sacc[14] = tot[14] + b3.z; sacc[15] = tot[15] + b3.w;
}

// in-lane squash: v = s * n2 / ((1+n2) sqrt(n2+eps))
__device__ __forceinline__ void squash_lane(const float* s, float* v)
{
    float n2 = 0.f;
    #pragma unroll
    for (int d = 0; d < 16; d++) n2 = fmaf(s[d], s[d], n2);
    float f = n2 / ((1.f + n2) * sqrtf(n2 + 1e-8f));
    #pragma unroll
    for (int d = 0; d < 16; d++) v[d] = s[d] * f;
}

__global__ void __launch_bounds__(256, 1) __cluster_dims__(2, 1, 1)
routing_kernel(float* __restrict__ out)
{
    extern __shared__ __align__(16) char smraw[];
    __half* sv     = reinterpret_cast<__half*>(smraw);             // 144x512 fp16
    float*  s_part = reinterpret_cast<float*>(smraw + SV_BYTES);   // 8x512
    float*  part   = s_part + 8 * JD;                              // [2][2][512]

    const int rank = blockIdx.x & 1;
    const int m    = blockIdx.x >> 1;
    const int t    = threadIdx.x;
    const int w    = t >> 5;
    const int j    = t & 31;
    const int k0   = w * ROWS_PW;

    const __half* base = g_votes + (size_t)m * (KKA * JD) + (size_t)rank * KHALF * JD;

    // ---- load half-tile into smem (single DRAM pass) ----
    {
        const uint4* g = reinterpret_cast<const uint4*>(base);
        uint4* s4 = reinterpret_cast<uint4*>(sv);
        #pragma unroll 4
        for (int i = t; i < SV_BYTES / 16; i += 256)
            s4[i] = g[i];
    }
    __syncthreads();

    float v[16];
    float logit[ROWS_PW];
    float sacc[16];

    // ================= iteration 1: s = (sum over all k) / 32 =================
    #pragma unroll
    for (int d = 0; d < 16; d++) sacc[d] = 0.f;
    {
        uint4 q0, q1;
        load_row(sv, k0, j, q0, q1);
        #pragma unroll
        for (int i = 0; i < ROWS_PW; i++) {
            uint4 c0 = q0, c1 = q1;
            if (i + 1 < ROWS_PW) load_row(sv, k0 + i + 1, j, q0, q1);
            float row[16];
            cvt_row(c0, c1, row);
            #pragma unroll
            for (int d = 0; d < 16; d++) sacc[d] += row[d];
        }
    }
    reduce_site(sacc, s_part, part, 0, rank, w, j, t);
    #pragma unroll
    for (int d = 0; d < 16; d++) sacc[d] *= (1.f / 32.f);
    squash_lane(sacc, v);                                          // v1

    // ================= iterations 2 and 3 =================
    #pragma unroll 1
    for (int iter = 0; iter < 2; iter++) {
        #pragma unroll
        for (int d = 0; d < 16; d++) sacc[d] = 0.f;
        uint4 q0, q1;
        load_row(sv, k0, j, q0, q1);
        #pragma unroll
        for (int i = 0; i < ROWS_PW; i++) {
            uint4 c0 = q0, c1 = q1;
            if (i + 1 < ROWS_PW) load_row(sv, k0 + i + 1, j, q0, q1);
            float row[16];
            cvt_row(c0, c1, row);
            // logits dot (serial over d, all in regs)
            float dlg = 0.f;
            #pragma unroll
            for (int d = 0; d < 16; d++) dlg = fmaf(row[d], v[d], dlg);
            float lg = (iter == 0) ? dlg : (logit[i] + dlg);
            logit[i] = lg;
            // softmax over j = 32 lanes (warp-local)
            float mx = lg;
            #pragma unroll
            for (int off = 16; off > 0; off >>= 1)
                mx = fmaxf(mx, __shfl_xor_sync(0xffffffffu, mx, off));
            float e = __expf(lg - mx);
            float sm = e;
            #pragma unroll
            for (int off = 16; off > 0; off >>= 1)
                sm += __shfl_xor_sync(0xffffffffu, sm, off);
            float c = e / sm;
            // s accumulation (c stays in lane)
            #pragma unroll
            for (int d = 0; d < 16; d++) sacc[d] = fmaf(c, row[d], sacc[d]);
        }
        reduce_site(sacc, s_part, part, 1 - iter, rank, w, j, t);
        squash_lane(sacc, v);                                      // v2 / v3
    }

    // output: out[b, jd, l]; rank 0, warp 0 writes (all warps hold identical v)
    if (rank == 0 && w == 0) {
        const int b = m / LPOS, l = m % LPOS;
        #pragma unroll
        for (int d = 0; d < 16; d++)
            out[((size_t)b * JD + 16 * j + d) * LPOS + l] = v[d];
    }
}

// ---------------------------------------------------------------------------
extern "C" void kernel_launch(void* const* d_in, const int* in_sizes, int n_in,
                              void* d_out, int out_size)
{
    const float* pose = (const float*)d_in[0];   // (4, 512, 32, 32)
    const float* W    = (const float*)d_in[1];   // (288, 512, 16)
    float* out        = (float*)d_out;           // (4, 512, 15, 15)

    cudaFuncSetAttribute(routing_kernel,
                         cudaFuncAttributeMaxDynamicSharedMemorySize,
                         K2_SMEM_BYTES);

    dim3 g1(KKA, MTOT / M_TILE);
    votes_kernel<<<g1, 256>>>(pose, W);
    routing_kernel<<<2 * MTOT, 256, K2_SMEM_BYTES>>>(out);
}

// round 13
// speedup vs baseline: 1.4005x; 1.3910x over previous
#include <cuda_runtime.h>
#include <cuda_fp16.h>
#include <cstdint>

// Problem constants
#define A_CAPS   32
#define CDIM     16
#define KKA      288          // 9 * 32
#define KHALF    144          // per cluster rank
#define NWARP    16
#define ROWS_PW  9            // KHALF / 16 warps
#define JD       512          // B*D
#define OH       15
#define OW       15
#define LPOS     225          // OH*OW
#define BATCH    4
#define MTOT     900          // BATCH * LPOS
#define M_TILE   60           // 900 / 60 = 15 tiles
#define WS_STR   516          // padded row stride for Ws [c][jd]

// K2 dynamic smem layout (bytes)
#define SV_BYTES   (KHALF * JD * 2)        // 147456 fp16 votes half-tile
#define SP_BYTES   (NWARP * JD * 4)        // 32768 cross-warp partials
#define PART_BYTES (2 * 2 * JD * 4)        // 8192  [buf][rank][jd] exchange
#define VS_BYTES   (JD * 4)                // 2048  v broadcast
#define K2_SMEM_BYTES (SV_BYTES + SP_BYTES + PART_BYTES + VS_BYTES)

// 265 MB votes scratch (fp16): [m][k][jd]
__device__ __align__(16) __half g_votes[(size_t)MTOT * KKA * JD];

// ---- packed f32x2 helpers (sm_103a) ----
__device__ __forceinline__ unsigned long long pk2(float x, float y) {
    unsigned long long r;
    asm("mov.b64 %0, {%1, %2};" : "=l"(r) : "f"(x), "f"(y));
    return r;
}
__device__ __forceinline__ unsigned long long ffma2(
    unsigned long long a, unsigned long long b, unsigned long long c) {
    unsigned long long d;
    asm("fma.rn.f32x2 %0, %1, %2, %3;" : "=l"(d) : "l"(a), "l"(b), "l"(c));
    return d;
}
__device__ __forceinline__ void upk2(unsigned long long v, float& lo, float& hi) {
    asm("mov.b64 {%0, %1}, %2;" : "=f"(lo), "=f"(hi) : "l"(v));
}
__device__ __forceinline__ uint32_t smem_u32(const void* p) {
    uint32_t a;
    asm("{ .reg .u64 t; cvta.to.shared.u64 t, %1; cvt.u32.u64 %0, t; }"
        : "=r"(a) : "l"(p));
    return a;
}

// ---------------------------------------------------------------------------
// K1 v4: 512 threads, 2 jd per thread (16 u64 W regs, no spill).
// votes[m][k][jd] = sum_c W[k][jd][c] * p[m][k][c]; f32x2 math, fp16 out.
// grid (KKA, MTOT/M_TILE)
// ---------------------------------------------------------------------------
__global__ void __launch_bounds__(512, 2) votes_kernel(
    const float* __restrict__ pose, const float* __restrict__ W)
{
    __shared__ __align__(16) float Ws[CDIM * WS_STR];              // [c][jd]
    __shared__ __align__(16) unsigned long long Ps2[M_TILE][CDIM]; // (p,p)

    const int k  = blockIdx.x;
    const int m0 = blockIdx.y * M_TILE;
    const int t  = threadIdx.x;

    // Stage W[k] (512x16) transposed into smem
    const float* Wk = W + (size_t)k * (JD * CDIM);
    for (int i = t; i < JD * CDIM; i += 512) {
        int jd = i >> 4, c = i & 15;
        Ws[c * WS_STR + jd] = Wk[i];
    }

    // Stage pose slices, pre-packed (p,p)
    const int a  = k & 31;
    const int kk = k >> 5;
    const int ki = kk / 3, kj = kk % 3;
    for (int i = t; i < M_TILE * CDIM; i += 512) {
        int mi = i >> 4, c = i & 15;
        int m  = m0 + mi;
        int b  = m / LPOS, l = m % LPOS;
        int oy = l / OW,   ox = l % OW;
        int y  = 2 * oy + ki, x = 2 * ox + kj;
        float p = pose[(((size_t)b * (A_CAPS * CDIM) + a * CDIM + c) * 32 + y) * 32 + x];
        Ps2[mi][c] = pk2(p, p);
    }
    __syncthreads();

    const int jp    = t & 255;     // jd pair: jd = 2*jp, 2*jp+1
    const int mslot = t >> 8;      // 0 or 1

    // Hoist W slice: 16 packed u64 (one-time)
    unsigned long long wreg[CDIM];
    #pragma unroll
    for (int c = 0; c < CDIM; c++) {
        float2 w2 = *reinterpret_cast<const float2*>(&Ws[c * WS_STR + 2 * jp]);
        wreg[c] = pk2(w2.x, w2.y);
    }

    #pragma unroll 2
    for (int q = 0; q < M_TILE / 2; q++) {
        const int mi = 2 * q + mslot;
        const ulonglong2* pp = reinterpret_cast<const ulonglong2*>(&Ps2[mi][0]);
        unsigned long long acc = 0ull;
        #pragma unroll
        for (int cc = 0; cc < CDIM / 2; cc++) {
            ulonglong2 p2 = pp[cc];
            acc = ffma2(wreg[2 * cc],     p2.x, acc);
            acc = ffma2(wreg[2 * cc + 1], p2.y, acc);
        }
        float x0, x1;
        upk2(acc, x0, x1);
        __half2 h = __floats2half2_rn(x0, x1);
        *reinterpret_cast<uint32_t*>(
            &g_votes[((size_t)(m0 + mi) * KKA + k) * JD + 2 * jp]) =
            *reinterpret_cast<uint32_t*>(&h);
    }
}

// ---------------------------------------------------------------------------
// K2 v4: 2-CTA cluster per site, 512 threads (16 warps x 9 rows).
// Warp w owns k-rows [9w, 9w+9); lane j owns capsule j (jd 16j..16j+15).
// Reductions are jd-parallel: thread t owns jd = t.
// ---------------------------------------------------------------------------

__device__ __forceinline__ void load_cvt_row(const __half* sv, int k, int j,
                                             float* row)
{
    const uint4* p = reinterpret_cast<const uint4*>(sv + k * JD + 16 * j);
    uint4 q0 = p[0], q1 = p[1];
    const uint32_t u[8] = {q0.x, q0.y, q0.z, q0.w, q1.x, q1.y, q1.z, q1.w};
    #pragma unroll
    for (int i = 0; i < 8; i++) {
        float2 f = __half22float2(*reinterpret_cast<const __half2*>(&u[i]));
        row[2 * i]     = f.x;
        row[2 * i + 1] = f.y;
    }
}

// Reduce 16 warps' partials + cross-rank; returns site total for jd = t.
__device__ __forceinline__ float reduce_site_jd(
    const float* sacc, float* s_part, float* part,
    int buf, int rank, int w, int j, int t)
{
    float4* dst = reinterpret_cast<float4*>(s_part + w * JD + 16 * j);
    dst[0] = make_float4(sacc[0], sacc[1], sacc[2],  sacc[3]);
    dst[1] = make_float4(sacc[4], sacc[5], sacc[6],  sacc[7]);
    dst[2] = make_float4(sacc[8], sacc[9], sacc[10], sacc[11]);
    dst[3] = make_float4(sacc[12], sacc[13], sacc[14], sacc[15]);
    __syncthreads();

    float tot = 0.f;
    #pragma unroll
    for (int ww = 0; ww < NWARP; ww++) tot += s_part[ww * JD + t];

    // publish rank slice locally + to peer
    float* slot = part + (buf * 2 + rank) * JD;
    slot[t] = tot;
    uint32_t la = smem_u32(&slot[t]);
    uint32_t bits = __float_as_uint(tot);
    asm volatile(
        "{ .reg .b32 r; mapa.shared::cluster.u32 r, %0, %1;"
        "  st.shared::cluster.b32 [r], %2; }"
        :: "r"(la), "r"(rank ^ 1), "r"(bits) : "memory");
    asm volatile("barrier.cluster.arrive.aligned;" ::: "memory");
    asm volatile("barrier.cluster.wait.aligned;" ::: "memory");

    return tot + part[(buf * 2 + (rank ^ 1)) * JD + t];
}

// squash in jd-domain: 16 consecutive jd (= one capsule) share a width-16 group
__device__ __forceinline__ float squash_jd(float s)
{
    float n2 = s * s;
    #pragma unroll
    for (int off = 8; off > 0; off >>= 1)
        n2 += __shfl_xor_sync(0xffffffffu, n2, off, 16);
    float f = n2 / ((1.f + n2) * sqrtf(n2 + 1e-8f));
    return s * f;
}

__global__ void __launch_bounds__(512, 1) __cluster_dims__(2, 1, 1)
routing_kernel(float* __restrict__ out)
{
    extern __shared__ __align__(16) char smraw[];
    __half* sv     = reinterpret_cast<__half*>(smraw);              // 144x512 fp16
    float*  s_part = reinterpret_cast<float*>(smraw + SV_BYTES);    // 16x512
    float*  part   = s_part + NWARP * JD;                           // [2][2][512]
    float*  v_s    = part + 2 * 2 * JD;                             // 512

    const int rank = blockIdx.x & 1;
    const int m    = blockIdx.x >> 1;
    const int t    = threadIdx.x;
    const int w    = t >> 5;
    const int j    = t & 31;
    const int k0   = w * ROWS_PW;

    const __half* base = g_votes + (size_t)m * (KKA * JD) + (size_t)rank * KHALF * JD;

    // ---- load half-tile into smem (single DRAM pass) ----
    {
        const uint4* g = reinterpret_cast<const uint4*>(base);
        uint4* s4 = reinterpret_cast<uint4*>(sv);
        #pragma unroll
        for (int i = 0; i < SV_BYTES / 16 / 512; i++)
            s4[t + i * 512] = g[t + i * 512];
    }
    __syncthreads();

    float sacc[16];
    float logit[ROWS_PW];
    float vt;   // v for jd = t

    // ================= iteration 1: s = (sum over all k) / 32 =================
    #pragma unroll
    for (int d = 0; d < 16; d++) sacc[d] = 0.f;
    #pragma unroll
    for (int i = 0; i < ROWS_PW; i++) {
        float row[16];
        load_cvt_row(sv, k0 + i, j, row);
        #pragma unroll
        for (int d = 0; d < 16; d++) sacc[d] += row[d];
    }
    {
        float tot = reduce_site_jd(sacc, s_part, part, 0, rank, w, j, t);
        vt = squash_jd(tot * (1.f / 32.f));
        v_s[t] = vt;
    }
    __syncthreads();

    // ================= iterations 2 and 3 =================
    #pragma unroll 1
    for (int iter = 0; iter < 2; iter++) {
        // reload v slice for lane's capsule
        float v[16];
        {
            const float4* vp = reinterpret_cast<const float4*>(v_s + 16 * j);
            float4 a0 = vp[0], a1 = vp[1], a2 = vp[2], a3 = vp[3];
            v[0]=a0.x; v[1]=a0.y; v[2]=a0.z;  v[3]=a0.w;
            v[4]=a1.x; v[5]=a1.y; v[6]=a1.z;  v[7]=a1.w;
            v[8]=a2.x; v[9]=a2.y; v[10]=a2.z; v[11]=a2.w;
            v[12]=a3.x; v[13]=a3.y; v[14]=a3.z; v[15]=a3.w;
        }
        #pragma unroll
        for (int d = 0; d < 16; d++) sacc[d] = 0.f;

        #pragma unroll
        for (int i = 0; i < ROWS_PW; i++) {
            float row[16];
            load_cvt_row(sv, k0 + i, j, row);
            float dlg = 0.f;
            #pragma unroll
            for (int d = 0; d < 16; d++) dlg = fmaf(row[d], v[d], dlg);
            float lg = (iter == 0) ? dlg : (logit[i] + dlg);
            logit[i] = lg;
            // softmax over 32 lanes WITHOUT max subtraction (|lg| <= ~8, safe)
            float e = __expf(lg);
            float sm = e;
            #pragma unroll
            for (int off = 16; off > 0; off >>= 1)
                sm += __shfl_xor_sync(0xffffffffu, sm, off);
            float c = __fdividef(e, sm);
            #pragma unroll
            for (int d = 0; d < 16; d++) sacc[d] = fmaf(c, row[d], sacc[d]);
        }
        float tot = reduce_site_jd(sacc, s_part, part, 1 - iter, rank, w, j, t);
        vt = squash_jd(tot);
        v_s[t] = vt;
        __syncthreads();
    }

    // output: out[b, jd, l]; jd = t. Only rank 0 writes.
    if (rank == 0) {
        const int b = m / LPOS, l = m % LPOS;
        out[((size_t)b * JD + t) * LPOS + l] = vt;
    }
}

// ---------------------------------------------------------------------------
extern "C" void kernel_launch(void* const* d_in, const int* in_sizes, int n_in,
                              void* d_out, int out_size)
{
    const float* pose = (const float*)d_in[0];   // (4, 512, 32, 32)
    const float* W    = (const float*)d_in[1];   // (288, 512, 16)
    float* out        = (float*)d_out;           // (4, 512, 15, 15)

    cudaFuncSetAttribute(routing_kernel,
                         cudaFuncAttributeMaxDynamicSharedMemorySize,
                         K2_SMEM_BYTES);

    dim3 g1(KKA, MTOT / M_TILE);
    votes_kernel<<<g1, 512>>>(pose, W);
    routing_kernel<<<2 * MTOT, 512, K2_SMEM_BYTES>>>(out);
}

// round 14
// speedup vs baseline: 1.4263x; 1.0184x over previous
#include <cuda_runtime.h>
#include <cuda_fp16.h>
#include <cstdint>

// Problem constants
#define A_CAPS   32
#define CDIM     16
#define KKA      288          // 9 * 32
#define KHALF    144          // per cluster rank
#define NWARP    16
#define ROWS_PW  9            // KHALF / 16 warps
#define JD       512          // B*D
#define OH       15
#define OW       15
#define LPOS     225          // OH*OW
#define BATCH    4
#define MTOT     900          // BATCH * LPOS
#define MT_M     48           // m-rows per K1 block
#define MBLK     19           // ceil(912/48); covers 912 >= 900

// K2 dynamic smem layout (bytes)
#define SV_BYTES   (KHALF * JD * 2)        // 147456 fp16 votes half-tile
#define SP_BYTES   (NWARP * JD * 4)        // 32768 cross-warp partials
#define PART_BYTES (2 * 2 * JD * 4)        // 8192  [buf][rank][jd] exchange
#define VS_BYTES   (JD * 4)                // 2048  v broadcast
#define K2_SMEM_BYTES (SV_BYTES + SP_BYTES + PART_BYTES + VS_BYTES)

// 265 MB votes scratch (fp16): [m][k][jd]
__device__ __align__(16) __half g_votes[(size_t)MTOT * KKA * JD];

__device__ __forceinline__ uint32_t smem_u32(const void* p) {
    uint32_t a;
    asm("{ .reg .u64 t; cvta.to.shared.u64 t, %1; cvt.u32.u64 %0, t; }"
        : "=r"(a) : "l"(p));
    return a;
}
__device__ __forceinline__ uint32_t h2bits(__half2 h) {
    return *reinterpret_cast<uint32_t*>(&h);
}

// ---------------------------------------------------------------------------
// K1 v5 (HMMA): votes[m][k][jd] = sum_c p[m][c] * W[k][jd][c]
// mma.sync.m16n8k16 f16xf16->f32. Block = one k, 48 m-rows, all 512 jd.
// 256 threads = 8 warps; warp w covers n-tiles [8w, 8w+8) x 3 m-tiles.
// grid (KKA, MBLK)
// ---------------------------------------------------------------------------
__global__ void __launch_bounds__(256) votes_kernel(
    const float* __restrict__ pose, const float* __restrict__ W)
{
    __shared__ uint32_t Wp[8][JD];     // [cpair][jd] half2(W[jd][2cp],W[jd][2cp+1])
    __shared__ uint32_t Pp[8][MT_M];   // [cpair][m]  half2(p[m][2cp],p[m][2cp+1])

    const int k  = blockIdx.x;
    const int m0 = blockIdx.y * MT_M;
    const int t  = threadIdx.x;

    // stage W[k] (512x16 fp32) as half2 pairs, cpair-major
    const float2* Wk2 = reinterpret_cast<const float2*>(W + (size_t)k * (JD * CDIM));
    #pragma unroll
    for (int i = t; i < JD * 8; i += 256) {
        int jd = i >> 3, cp = i & 7;
        float2 w = Wk2[jd * 8 + cp];
        Wp[cp][jd] = h2bits(__floats2half2_rn(w.x, w.y));
    }

    // stage pose slice (48 m x 16 c) as half2 pairs
    const int a  = k & 31;
    const int kk = k >> 5;
    const int ki = kk / 3, kj = kk % 3;
    for (int i = t; i < MT_M * 8; i += 256) {
        int mi = i >> 3, cp = i & 7;
        int m  = m0 + mi;
        float px = 0.f, py = 0.f;
        if (m < MTOT) {
            int b = m / LPOS, l = m % LPOS;
            int oy = l / OW,  ox = l % OW;
            int y = 2 * oy + ki, x = 2 * ox + kj;
            const float* pb = pose + ((size_t)b * (A_CAPS * CDIM) + a * CDIM) * 1024
                            + y * 32 + x;
            px = pb[(2 * cp)     * 1024];
            py = pb[(2 * cp + 1) * 1024];
        }
        Pp[cp][mi] = h2bits(__floats2half2_rn(px, py));
    }
    __syncthreads();

    const int w    = t >> 5;
    const int lane = t & 31;
    const int gid  = lane >> 2;   // 0..7
    const int tig  = lane & 3;    // 0..3

    // A fragments for the 3 m-tiles (held in regs)
    uint32_t afr[3][4];
    #pragma unroll
    for (int mt = 0; mt < 3; mt++) {
        int mr = mt * 16 + gid;
        afr[mt][0] = Pp[tig][mr];
        afr[mt][1] = Pp[tig][mr + 8];
        afr[mt][2] = Pp[tig + 4][mr];
        afr[mt][3] = Pp[tig + 4][mr + 8];
    }

    __half* vbase = g_votes + (size_t)k * JD;   // + m*(KKA*JD) later
    #pragma unroll
    for (int nt = 0; nt < 8; nt++) {
        const int jd0 = (w * 8 + nt) * 8;
        const uint32_t b0 = Wp[tig][jd0 + gid];
        const uint32_t b1 = Wp[tig + 4][jd0 + gid];
        #pragma unroll
        for (int mt = 0; mt < 3; mt++) {
            float d0, d1, d2, d3;
            asm volatile(
                "mma.sync.aligned.m16n8k16.row.col.f32.f16.f16.f32 "
                "{%0,%1,%2,%3}, {%4,%5,%6,%7}, {%8,%9}, {%10,%11,%12,%13};"
                : "=f"(d0), "=f"(d1), "=f"(d2), "=f"(d3)
                : "r"(afr[mt][0]), "r"(afr[mt][1]), "r"(afr[mt][2]), "r"(afr[mt][3]),
                  "r"(b0), "r"(b1),
                  "f"(0.f), "f"(0.f), "f"(0.f), "f"(0.f));
            const int m_lo = m0 + mt * 16 + gid;
            const int col  = jd0 + 2 * tig;
            if (m_lo < MTOT) {
                __half2 h = __floats2half2_rn(d0, d1);
                *reinterpret_cast<uint32_t*>(
                    vbase + (size_t)m_lo * (KKA * JD) + col) = h2bits(h);
            }
            if (m_lo + 8 < MTOT) {
                __half2 h = __floats2half2_rn(d2, d3);
                *reinterpret_cast<uint32_t*>(
                    vbase + (size_t)(m_lo + 8) * (KKA * JD) + col) = h2bits(h);
            }
        }
    }
}

// ---------------------------------------------------------------------------
// K2 v4 (unchanged, measured 161.9us): 2-CTA cluster per site, 512 threads.
// Warp w owns k-rows [9w, 9w+9); lane j owns capsule j. jd-parallel reductions.
// ---------------------------------------------------------------------------

__device__ __forceinline__ void load_cvt_row(const __half* sv, int k, int j,
                                             float* row)
{
    const uint4* p = reinterpret_cast<const uint4*>(sv + k * JD + 16 * j);
    uint4 q0 = p[0], q1 = p[1];
    const uint32_t u[8] = {q0.x, q0.y, q0.z, q0.w, q1.x, q1.y, q1.z, q1.w};
    #pragma unroll
    for (int i = 0; i < 8; i++) {
        float2 f = __half22float2(*reinterpret_cast<const __half2*>(&u[i]));
        row[2 * i]     = f.x;
        row[2 * i + 1] = f.y;
    }
}

__device__ __forceinline__ float reduce_site_jd(
    const float* sacc, float* s_part, float* part,
    int buf, int rank, int w, int j, int t)
{
    float4* dst = reinterpret_cast<float4*>(s_part + w * JD + 16 * j);
    dst[0] = make_float4(sacc[0], sacc[1], sacc[2],  sacc[3]);
    dst[1] = make_float4(sacc[4], sacc[5], sacc[6],  sacc[7]);
    dst[2] = make_float4(sacc[8], sacc[9], sacc[10], sacc[11]);
    dst[3] = make_float4(sacc[12], sacc[13], sacc[14], sacc[15]);
    __syncthreads();

    float tot = 0.f;
    #pragma unroll
    for (int ww = 0; ww < NWARP; ww++) tot += s_part[ww * JD + t];

    float* slot = part + (buf * 2 + rank) * JD;
    slot[t] = tot;
    uint32_t la = smem_u32(&slot[t]);
    uint32_t bits = __float_as_uint(tot);
    asm volatile(
        "{ .reg .b32 r; mapa.shared::cluster.u32 r, %0, %1;"
        "  st.shared::cluster.b32 [r], %2; }"
        :: "r"(la), "r"(rank ^ 1), "r"(bits) : "memory");
    asm volatile("barrier.cluster.arrive.aligned;" ::: "memory");
    asm volatile("barrier.cluster.wait.aligned;" ::: "memory");

    return tot + part[(buf * 2 + (rank ^ 1)) * JD + t];
}

__device__ __forceinline__ float squash_jd(float s)
{
    float n2 = s * s;
    #pragma unroll
    for (int off = 8; off > 0; off >>= 1)
        n2 += __shfl_xor_sync(0xffffffffu, n2, off, 16);
    float f = n2 / ((1.f + n2) * sqrtf(n2 + 1e-8f));
    return s * f;
}

__global__ void __launch_bounds__(512, 1) __cluster_dims__(2, 1, 1)
routing_kernel(float* __restrict__ out)
{
    extern __shared__ __align__(16) char smraw[];
    __half* sv     = reinterpret_cast<__half*>(smraw);              // 144x512 fp16
    float*  s_part = reinterpret_cast<float*>(smraw + SV_BYTES);    // 16x512
    float*  part   = s_part + NWARP * JD;                           // [2][2][512]
    float*  v_s    = part + 2 * 2 * JD;                             // 512

    const int rank = blockIdx.x & 1;
    const int m    = blockIdx.x >> 1;
    const int t    = threadIdx.x;
    const int w    = t >> 5;
    const int j    = t & 31;
    const int k0   = w * ROWS_PW;

    const __half* base = g_votes + (size_t)m * (KKA * JD) + (size_t)rank * KHALF * JD;

    {
        const uint4* g = reinterpret_cast<const uint4*>(base);
        uint4* s4 = reinterpret_cast<uint4*>(sv);
        #pragma unroll
        for (int i = 0; i < SV_BYTES / 16 / 512; i++)
            s4[t + i * 512] = g[t + i * 512];
    }
    __syncthreads();

    float sacc[16];
    float logit[ROWS_PW];
    float vt;

    // iteration 1
    #pragma unroll
    for (int d = 0; d < 16; d++) sacc[d] = 0.f;
    #pragma unroll
    for (int i = 0; i < ROWS_PW; i++) {
        float row[16];
        load_cvt_row(sv, k0 + i, j, row);
        #pragma unroll
        for (int d = 0; d < 16; d++) sacc[d] += row[d];
    }
    {
        float tot = reduce_site_jd(sacc, s_part, part, 0, rank, w, j, t);
        vt = squash_jd(tot * (1.f / 32.f));
        v_s[t] = vt;
    }
    __syncthreads();

    // iterations 2 and 3
    #pragma unroll 1
    for (int iter = 0; iter < 2; iter++) {
        float v[16];
        {
            const float4* vp = reinterpret_cast<const float4*>(v_s + 16 * j);
            float4 a0 = vp[0], a1 = vp[1], a2 = vp[2], a3 = vp[3];
            v[0]=a0.x; v[1]=a0.y; v[2]=a0.z;  v[3]=a0.w;
            v[4]=a1.x; v[5]=a1.y; v[6]=a1.z;  v[7]=a1.w;
            v[8]=a2.x; v[9]=a2.y; v[10]=a2.z; v[11]=a2.w;
            v[12]=a3.x; v[13]=a3.y; v[14]=a3.z; v[15]=a3.w;
        }
        #pragma unroll
        for (int d = 0; d < 16; d++) sacc[d] = 0.f;

        #pragma unroll
        for (int i = 0; i < ROWS_PW; i++) {
            float row[16];
            load_cvt_row(sv, k0 + i, j, row);
            float dlg = 0.f;
            #pragma unroll
            for (int d = 0; d < 16; d++) dlg = fmaf(row[d], v[d], dlg);
            float lg = (iter == 0) ? dlg : (logit[i] + dlg);
            logit[i] = lg;
            float e = __expf(lg);
            float sm = e;
            #pragma unroll
            for (int off = 16; off > 0; off >>= 1)
                sm += __shfl_xor_sync(0xffffffffu, sm, off);
            float c = __fdividef(e, sm);
            #pragma unroll
            for (int d = 0; d < 16; d++) sacc[d] = fmaf(c, row[d], sacc[d]);
        }
        float tot = reduce_site_jd(sacc, s_part, part, 1 - iter, rank, w, j, t);
        vt = squash_jd(tot);
        v_s[t] = vt;
        __syncthreads();
    }

    if (rank == 0) {
        const int b = m / LPOS, l = m % LPOS;
        out[((size_t)b * JD + t) * LPOS + l] = vt;
    }
}

// ---------------------------------------------------------------------------
extern "C" void kernel_launch(void* const* d_in, const int* in_sizes, int n_in,
                              void* d_out, int out_size)
{
    const float* pose = (const float*)d_in[0];   // (4, 512, 32, 32)
    const float* W    = (const float*)d_in[1];   // (288, 512, 16)
    float* out        = (float*)d_out;           // (4, 512, 15, 15)

    cudaFuncSetAttribute(routing_kernel,
                         cudaFuncAttributeMaxDynamicSharedMemorySize,
                         K2_SMEM_BYTES);

    dim3 g1(KKA, MBLK);
    votes_kernel<<<g1, 256>>>(pose, W);
    routing_kernel<<<2 * MTOT, 512, K2_SMEM_BYTES>>>(out);
}